// round 1
// baseline (speedup 1.0000x reference)
#include <cuda_runtime.h>
#include <cuda_bf16.h>
#include <cstdint>

// Problem dims
#define NB 512
#define NS 32
#define NH 512
#define ND 256
#define NC 128

// ---------------- scratch (device globals; no allocation) ----------------
__device__ unsigned long long g_packed[NH * NB];  // [h][b] packed (ordval<<32)|~s
__device__ float g_hTop[NB * NH];                 // relu(max) [b][h]
__device__ int   g_cnt[NH * NS];                  // argmax histogram
__device__ float g_meanUpd[ND];
__device__ float g_lossRow[NB];
__device__ float g_corrRow[NB];

// order-preserving float <-> uint
__device__ __forceinline__ unsigned ord_encode(float f) {
    unsigned i = __float_as_uint(f);
    return (i & 0x80000000u) ? ~i : (i | 0x80000000u);
}
__device__ __forceinline__ float ord_decode(unsigned u) {
    unsigned i = (u & 0x80000000u) ? (u & 0x7FFFFFFFu) : ~u;
    return __uint_as_float(i);
}

// ---------------- init ----------------
__global__ void init_kernel(float* out) {
    int i = blockIdx.x * blockDim.x + threadIdx.x;
    if (i < NH * NB) g_packed[i] = 0ull;
    if (i < NH * NS) g_cnt[i] = 0;
    if (i == 0) { out[0] = 0.f; out[1] = 0.f; }
}

// ---------------- mean Hebbian update term ----------------
__global__ void meanupd_kernel(const float* __restrict__ x) {
    int d = threadIdx.x;  // 256
    float acc = 0.f;
    #pragma unroll 8
    for (int b = 0; b < NB; ++b) {
        float v = x[b * ND + d];
        acc += (v > 0.f ? 1.f : 0.f) - (v < 0.f ? 1.f : 0.f);
    }
    g_meanUpd[d] = acc * (0.001f / (float)NB);
}

// ---------------- main GEMM + fused max/argmax over S ----------------
// grid (H/64, B/64, 4 s-splits), 256 threads, 4x4 per thread
__global__ __launch_bounds__(256, 2)
void gemm_max_kernel(const float* __restrict__ x, const float* __restrict__ W0,
                     const float* __restrict__ b0) {
    __shared__ float xs[32][68];  // [d][b]  (68: pad, keeps 16B alignment + kills read conflicts)
    __shared__ float ws[32][68];  // [d][h]
    const int hTile = blockIdx.x * 64;
    const int bTile = blockIdx.y * 64;
    const int sBase = blockIdx.z * 8;
    const int tid = threadIdx.x;
    const int tx = tid & 15, ty = tid >> 4;
    const int bo = ty * 4, ho = tx * 4;
    const int ldd = tid & 31;  // d lane for loads
    const int ldr = tid >> 5;  // row base 0..7

    float maxv[4][4];
    int   maxs[4][4];
    #pragma unroll
    for (int i = 0; i < 4; ++i)
        #pragma unroll
        for (int j = 0; j < 4; ++j) { maxv[i][j] = -3.4e38f; maxs[i][j] = 0; }

    for (int s = 0; s < 8; ++s) {
        const int sIdx = sBase + s;
        const float* W0s = W0 + (size_t)sIdx * (NH * ND);
        float acc[4][4];
        #pragma unroll
        for (int i = 0; i < 4; ++i)
            #pragma unroll
            for (int j = 0; j < 4; ++j) acc[i][j] = 0.f;

        for (int dk = 0; dk < 8; ++dk) {
            const int dBase = dk * 32;
            #pragma unroll
            for (int p = 0; p < 8; ++p) {
                int row = ldr + p * 8;
                xs[ldd][row] = x[(bTile + row) * ND + dBase + ldd];
                ws[ldd][row] = W0s[(hTile + row) * ND + dBase + ldd];
            }
            __syncthreads();
            #pragma unroll
            for (int d = 0; d < 32; ++d) {
                float4 xv = *(const float4*)&xs[d][bo];
                float4 wv = *(const float4*)&ws[d][ho];
                float xa[4] = {xv.x, xv.y, xv.z, xv.w};
                float wa[4] = {wv.x, wv.y, wv.z, wv.w};
                #pragma unroll
                for (int i = 0; i < 4; ++i)
                    #pragma unroll
                    for (int j = 0; j < 4; ++j)
                        acc[i][j] = fmaf(xa[i], wa[j], acc[i][j]);
            }
            __syncthreads();
        }
        // add bias, update running max/argmax
        #pragma unroll
        for (int j = 0; j < 4; ++j) {
            float bv = __ldg(&b0[sIdx * NH + hTile + ho + j]);
            #pragma unroll
            for (int i = 0; i < 4; ++i) {
                float v = acc[i][j] + bv;
                if (v > maxv[i][j]) { maxv[i][j] = v; maxs[i][j] = sIdx; }
            }
        }
    }
    // merge across s-splits; ~s so ties pick lowest s (matches jnp.argmax)
    #pragma unroll
    for (int i = 0; i < 4; ++i)
        #pragma unroll
        for (int j = 0; j < 4; ++j) {
            unsigned long long pk =
                ((unsigned long long)ord_encode(maxv[i][j]) << 32) |
                (unsigned)(~maxs[i][j]);
            atomicMax(&g_packed[(size_t)(hTile + ho + j) * NB + (bTile + bo + i)], pk);
        }
}

// ---------------- decode packed -> relu'd hTop (transposed) + histogram ----------------
// grid (8,8) tiles of 64h x 64b, 256 threads
__global__ void hist_transpose_kernel() {
    __shared__ float tile[64][65];
    const int hT = blockIdx.x * 64;
    const int bT = blockIdx.y * 64;
    const int tid = threadIdx.x;
    #pragma unroll
    for (int k = 0; k < 16; ++k) {
        int e = tid + k * 256;
        int hl = e >> 6, bl = e & 63;
        unsigned long long p = g_packed[(size_t)(hT + hl) * NB + bT + bl];
        unsigned s = (~(unsigned)(p & 0xFFFFFFFFu)) & 31u;
        float v = ord_decode((unsigned)(p >> 32));
        tile[bl][hl] = v > 0.f ? v : 0.f;
        atomicAdd(&g_cnt[(hT + hl) * NS + (int)s], 1);
    }
    __syncthreads();
    #pragma unroll
    for (int k = 0; k < 16; ++k) {
        int e = tid + k * 256;
        int bl = e >> 6, hl = e & 63;
        g_hTop[(size_t)(bT + bl) * NH + hT + hl] = tile[bl][hl];
    }
}

// ---------------- topKweights via histogram-weighted W0 combination ----------------
// grid 512 (h), 256 threads (d)
__global__ void topkw_kernel(const float* __restrict__ W0, float* __restrict__ out) {
    const int h = blockIdx.x;
    const int d = threadIdx.x;
    __shared__ float cs[NS];
    if (d < NS) cs[d] = (float)g_cnt[h * NS + d];
    __syncthreads();
    float acc = 0.f;
    #pragma unroll
    for (int s = 0; s < NS; ++s)
        acc = fmaf(cs[s], W0[(size_t)s * (NH * ND) + h * ND + d], acc);
    out[2 + NB * NC + h * ND + d] = acc * (1.f / (float)NB) + g_meanUpd[d];
}

// ---------------- logits + log_softmax + per-row loss/correct ----------------
// grid 128 (4 b-rows each), 128 threads (c)
__global__ __launch_bounds__(128)
void out_kernel(const float* __restrict__ W1, const float* __restrict__ b1,
                const int* __restrict__ y, float* __restrict__ out) {
    __shared__ float sh[4][NH];
    __shared__ float w1s[NC][33];
    __shared__ unsigned long long redp[NC];
    __shared__ float redf[NC];
    const int bBase = blockIdx.x * 4;
    const int c = threadIdx.x;

    #pragma unroll
    for (int bi = 0; bi < 4; ++bi)
        #pragma unroll
        for (int k = 0; k < 4; ++k)
            sh[bi][c + k * NC] = g_hTop[(size_t)(bBase + bi) * NH + c + k * NC];

    float acc[4];
    float bias = b1[c];
    #pragma unroll
    for (int bi = 0; bi < 4; ++bi) acc[bi] = bias;

    for (int hc = 0; hc < NH / 32; ++hc) {
        __syncthreads();
        #pragma unroll
        for (int k = 0; k < 32; ++k) {
            int e = c + k * NC;       // 0..4095
            int cc = e >> 5, jj = e & 31;
            w1s[cc][jj] = W1[cc * NH + hc * 32 + jj];
        }
        __syncthreads();
        #pragma unroll
        for (int j = 0; j < 32; ++j) {
            float w = w1s[c][j];
            int hh = hc * 32 + j;
            #pragma unroll
            for (int bi = 0; bi < 4; ++bi)
                acc[bi] = fmaf(sh[bi][hh], w, acc[bi]);
        }
    }
    __syncthreads();

    for (int bi = 0; bi < 4; ++bi) {
        const int b = bBase + bi;
        const float lg = acc[bi];
        // max + argmax (ties -> lowest c, matching jnp.argmax)
        unsigned long long pk =
            ((unsigned long long)ord_encode(lg) << 32) | (unsigned)(NC - 1 - c);
        redp[c] = pk;
        __syncthreads();
        for (int off = NC / 2; off > 0; off >>= 1) {
            if (c < off) { if (redp[c + off] > redp[c]) redp[c] = redp[c + off]; }
            __syncthreads();
        }
        unsigned long long pmax = redp[0];
        float m = ord_decode((unsigned)(pmax >> 32));
        int cmax = NC - 1 - (int)(pmax & 0xFFFFFFFFu);
        __syncthreads();
        // sum of exp
        redf[c] = expf(lg - m);
        __syncthreads();
        for (int off = NC / 2; off > 0; off >>= 1) {
            if (c < off) redf[c] += redf[c + off];
            __syncthreads();
        }
        float lse = logf(redf[0]);
        float lp = lg - m - lse;
        out[2 + b * NC + c] = lp;
        int yb = y[b];
        if (c == yb) g_lossRow[b] = -lp;
        if (c == 0)  g_corrRow[b] = (cmax == yb) ? 1.f : 0.f;
        __syncthreads();
    }
}

// ---------------- deterministic final reductions ----------------
__global__ void finalize_kernel(float* out) {
    __shared__ float sl[NB], sc[NB];
    int t = threadIdx.x;
    sl[t] = g_lossRow[t];
    sc[t] = g_corrRow[t];
    __syncthreads();
    for (int off = NB / 2; off > 0; off >>= 1) {
        if (t < off) { sl[t] += sl[t + off]; sc[t] += sc[t + off]; }
        __syncthreads();
    }
    if (t == 0) { out[0] = sl[0] / (float)NB; out[1] = sc[0] / (float)NB; }
}

// ---------------- launcher ----------------
extern "C" void kernel_launch(void* const* d_in, const int* in_sizes, int n_in,
                              void* d_out, int out_size) {
    const float* x  = (const float*)d_in[0];
    const int*   y  = (const int*)d_in[1];
    const float* W0 = (const float*)d_in[2];
    const float* b0 = (const float*)d_in[3];
    const float* W1 = (const float*)d_in[4];
    const float* b1 = (const float*)d_in[5];
    float* out = (float*)d_out;

    init_kernel<<<(NH * NB + 255) / 256, 256>>>(out);
    meanupd_kernel<<<1, ND>>>(x);
    gemm_max_kernel<<<dim3(NH / 64, NB / 64, 4), 256>>>(x, W0, b0);
    hist_transpose_kernel<<<dim3(NH / 64, NB / 64), 256>>>();
    topkw_kernel<<<NH, ND>>>(W0, out);
    out_kernel<<<NB / 4, NC>>>(W1, b1, y, out);
    finalize_kernel<<<1, NB>>>(out);
}

// round 3
// speedup vs baseline: 1.9145x; 1.9145x over previous
#include <cuda_runtime.h>
#include <cuda_bf16.h>
#include <cstdint>

#define NB 512
#define NS 32
#define NH 512
#define ND 256
#define NC 128
#define KEXT 768          // 3 x 256 (bf16x3 emulation folded into K)
#define CAND_CAP 16384
#define CAND_THR 1e-4f

// ---------------- device scratch (static, no allocation) ----------------
__device__ __nv_bfloat16 g_Aext[NB * KEXT];                 // [b][768] = [xh|xh|xl]
__device__ __nv_bfloat16 g_Bext[(size_t)NS * NH * KEXT];    // [s*512+h][768] = [wh|wl|wh]
__device__ float g_hTop[NB * NH];                           // relu(max_s z) [b][h]
__device__ int   g_cnt[NH * NS];                            // argmax histogram
__device__ float g_meanUpd[ND];                             // raw signed counts
__device__ float g_lossRow[NB];
__device__ float g_corrRow[NB];
__device__ int   g_candCount;
__device__ int4  g_cand[CAND_CAP];                          // (b, h, s1, 0)

// ---------------- PTX helpers (sm_100-plain safe: sm_80+ features only) ----
__device__ __forceinline__ uint32_t smem_u32(const void* p) {
    uint32_t a;
    asm("{ .reg .u64 t; cvta.to.shared.u64 t, %1; cvt.u32.u64 %0, t; }" : "=r"(a) : "l"(p));
    return a;
}
#define CP_ASYNC16(dst, src) \
    asm volatile("cp.async.cg.shared.global [%0], [%1], 16;" :: "r"(dst), "l"(src) : "memory")
#define CP_COMMIT() asm volatile("cp.async.commit_group;" ::: "memory")
#define CP_WAIT_GROUP(n) asm volatile("cp.async.wait_group %0;" :: "n"(n) : "memory")

__device__ __forceinline__ void ldsm4(uint32_t* r, uint32_t addr) {
    asm volatile("ldmatrix.sync.aligned.m8n8.x4.shared.b16 {%0,%1,%2,%3}, [%4];"
        : "=r"(r[0]), "=r"(r[1]), "=r"(r[2]), "=r"(r[3]) : "r"(addr));
}
__device__ __forceinline__ void mma16816(float* c, const uint32_t* a, const uint32_t* b) {
    asm volatile("mma.sync.aligned.m16n8k16.row.col.f32.bf16.bf16.f32 "
        "{%0,%1,%2,%3}, {%4,%5,%6,%7}, {%8,%9}, {%0,%1,%2,%3};"
        : "+f"(c[0]), "+f"(c[1]), "+f"(c[2]), "+f"(c[3])
        : "r"(a[0]), "r"(a[1]), "r"(a[2]), "r"(a[3]), "r"(b[0]), "r"(b[1]));
}

// swizzled 16B-slot offset inside a [rows][32B] tile (2 slots/row)
__device__ __forceinline__ uint32_t phys32(int row, int c) {
    return (uint32_t)(row * 32 + ((c ^ ((row >> 2) & 1)) << 4));
}

// ---------------- bf16 split convert: x -> A_ext ----------------
__global__ void convx_kernel(const float* __restrict__ x) {
    int p = blockIdx.x * blockDim.x + threadIdx.x;  // pairs
    int b = p >> 7, d2 = p & 127;
    float2 v = *(const float2*)(x + b * ND + 2 * d2);
    __nv_bfloat16 h0 = __float2bfloat16_rn(v.x);
    __nv_bfloat16 h1 = __float2bfloat16_rn(v.y);
    __nv_bfloat16 l0 = __float2bfloat16_rn(v.x - __bfloat162float(h0));
    __nv_bfloat16 l1 = __float2bfloat16_rn(v.y - __bfloat162float(h1));
    __nv_bfloat162 hh; hh.x = h0; hh.y = h1;
    __nv_bfloat162 ll; ll.x = l0; ll.y = l1;
    __nv_bfloat162* base = (__nv_bfloat162*)(g_Aext + b * KEXT);
    base[d2] = hh; base[128 + d2] = hh; base[256 + d2] = ll;
}

// ---------------- W0 -> B_ext (+ zero scratch piggyback) ----------------
__global__ void convw_kernel(const float* __restrict__ W0) {
    int bid = blockIdx.x, tid = threadIdx.x;
    if (bid < 16) {
        #pragma unroll
        for (int j = 0; j < 4; ++j) g_cnt[bid * 1024 + j * 256 + tid] = 0;
    } else if (bid == 16) {
        g_meanUpd[tid] = 0.f;
        if (tid == 0) g_candCount = 0;
    }
    int p = bid * 256 + tid;
    int row = p >> 7, d2 = p & 127;   // row = s*512+h
    float2 v = *(const float2*)(W0 + (size_t)row * ND + 2 * d2);
    __nv_bfloat16 h0 = __float2bfloat16_rn(v.x);
    __nv_bfloat16 h1 = __float2bfloat16_rn(v.y);
    __nv_bfloat16 l0 = __float2bfloat16_rn(v.x - __bfloat162float(h0));
    __nv_bfloat16 l1 = __float2bfloat16_rn(v.y - __bfloat162float(h1));
    __nv_bfloat162 hh; hh.x = h0; hh.y = h1;
    __nv_bfloat162 ll; ll.x = l0; ll.y = l1;
    __nv_bfloat162* base = (__nv_bfloat162*)(g_Bext + (size_t)row * KEXT);
    base[d2] = hh; base[128 + d2] = ll; base[256 + d2] = hh;
}

// ---------------- mean Hebbian update ----------------
__global__ void meanupd_kernel(const float* __restrict__ x) {
    int d = threadIdx.x;
    int b0i = blockIdx.x * 32;
    float acc = 0.f;
    #pragma unroll 8
    for (int b = 0; b < 32; ++b) {
        float v = x[(b0i + b) * ND + d];
        acc += (v > 0.f ? 1.f : 0.f) - (v < 0.f ? 1.f : 0.f);
    }
    atomicAdd(&g_meanUpd[d], acc);
}

// ---------------- mma.sync GEMM + fused max/argmax epilogue ----------------
// grid (64 h-tiles, 4 b-tiles), 256 threads (8 warps: 2 wb x 4 wn).
// CTA tile 128 b x 256 n, n = s*8 + hl (8 h, all 32 s). Warp tile 64x64.
// K: 48 chunks of 16, 4-stage cp.async ring. Stage: A 4KB + B 8KB = 12KB.
#define NCHUNK 48
#define STAGE_B 12288

__global__ __launch_bounds__(256, 1)
void gemm_mma_kernel(const float* __restrict__ b0) {
    __shared__ char sm[4 * STAGE_B];  // 48KB, reused by epilogue
    const uint32_t sbase = smem_u32(sm);
    const int tid = threadIdx.x;
    const int lane = tid & 31, warp = tid >> 5;
    const int wb = warp >> 2, wn = warp & 3;
    const int hBase = blockIdx.x * 8;
    const int bTile = blockIdx.y * 128;

    // ---- producer per-thread fixed mapping (1 A op + 2 B ops per chunk) ----
    const int rA = tid >> 1, cA = tid & 1;
    const int n1 = tid >> 1, n2 = 128 + (tid >> 1);
    const uint32_t dA  = phys32(rA, cA);
    const uint32_t dB1 = 4096 + phys32(n1, cA);
    const uint32_t dB2 = 4096 + phys32(n2, cA);
    const __nv_bfloat16* srcA  = g_Aext + (size_t)(bTile + rA) * KEXT + cA * 8;
    const __nv_bfloat16* srcB1 = g_Bext + (size_t)((n1 >> 3) * NH + hBase + (n1 & 7)) * KEXT + cA * 8;
    const __nv_bfloat16* srcB2 = g_Bext + (size_t)((n2 >> 3) * NH + hBase + (n2 & 7)) * KEXT + cA * 8;

    // ---- ldsm per-thread offsets (stage-relative) ----
    uint32_t aOff[4], bOff[4];
    {
        const int arow = (lane & 15), ac = lane >> 4;
        #pragma unroll
        for (int mb = 0; mb < 4; ++mb) {
            int row = wb * 64 + mb * 16 + arow;
            aOff[mb] = phys32(row, ac);
        }
        const int brow = ((lane >> 4) << 3) + (lane & 7), bc = (lane >> 3) & 1;
        #pragma unroll
        for (int jb = 0; jb < 4; ++jb) {
            int n = wn * 64 + jb * 16 + brow;
            bOff[jb] = 4096 + phys32(n, bc);
        }
    }

    float acc[4][8][4];
    #pragma unroll
    for (int mb = 0; mb < 4; ++mb)
        #pragma unroll
        for (int nb = 0; nb < 8; ++nb)
            #pragma unroll
            for (int q = 0; q < 4; ++q) acc[mb][nb][q] = 0.f;

    // ---- prologue: 3 chunks in flight ----
    #pragma unroll
    for (int p = 0; p < 3; ++p) {
        uint32_t st = sbase + p * STAGE_B;
        CP_ASYNC16(st + dA,  srcA  + p * 16);
        CP_ASYNC16(st + dB1, srcB1 + p * 16);
        CP_ASYNC16(st + dB2, srcB2 + p * 16);
        CP_COMMIT();
    }

    // ---- mainloop ----
    for (int c = 0; c < NCHUNK; ++c) {
        CP_WAIT_GROUP(2);
        __syncthreads();
        if (c + 3 < NCHUNK) {
            uint32_t st = sbase + ((c + 3) & 3) * STAGE_B;
            CP_ASYNC16(st + dA,  srcA  + (c + 3) * 16);
            CP_ASYNC16(st + dB1, srcB1 + (c + 3) * 16);
            CP_ASYNC16(st + dB2, srcB2 + (c + 3) * 16);
        }
        CP_COMMIT();

        const uint32_t base = sbase + (c & 3) * STAGE_B;
        uint32_t af[4][4], bf[4][4];
        #pragma unroll
        for (int mb = 0; mb < 4; ++mb) ldsm4(af[mb], base + aOff[mb]);
        #pragma unroll
        for (int jb = 0; jb < 4; ++jb) ldsm4(bf[jb], base + bOff[jb]);
        #pragma unroll
        for (int mb = 0; mb < 4; ++mb)
            #pragma unroll
            for (int jb = 0; jb < 4; ++jb) {
                mma16816(acc[mb][jb * 2],     af[mb], &bf[jb][0]);
                mma16816(acc[mb][jb * 2 + 1], af[mb], &bf[jb][2]);
            }
    }
    __syncthreads();

    // ---- epilogue phase 1: per-warp top-2 over this warp's 8 s ----
    float* v1s = (float*)sm;             // [4 wn][1024]
    int*   s1s = (int*)(sm + 16384);
    float* v2s = (float*)(sm + 32768);

    float biasv[8][2];
    #pragma unroll
    for (int nb = 0; nb < 8; ++nb)
        #pragma unroll
        for (int q = 0; q < 2; ++q)
            biasv[nb][q] = __ldg(&b0[(wn * 8 + nb) * NH + hBase + (lane & 3) * 2 + q]);

    #pragma unroll
    for (int mb = 0; mb < 4; ++mb)
        #pragma unroll
        for (int half = 0; half < 2; ++half)
            #pragma unroll
            for (int q = 0; q < 2; ++q) {
                float m1 = -3.4e38f, m2 = -3.4e38f; int s1 = 0;
                #pragma unroll
                for (int nb = 0; nb < 8; ++nb) {
                    float v = acc[mb][nb][half * 2 + q] + biasv[nb][q];
                    if (v > m1) { m2 = m1; m1 = v; s1 = wn * 8 + nb; }
                    else if (v > m2) m2 = v;
                }
                int row = wb * 64 + mb * 16 + half * 8 + (lane >> 2);
                int hl = (lane & 3) * 2 + q;
                int e = row * 8 + hl;
                v1s[wn * 1024 + e] = m1;
                s1s[wn * 1024 + e] = s1;
                v2s[wn * 1024 + e] = m2;
            }
    __syncthreads();

    // ---- epilogue phase 2: cross-warp combine, write hTop, hist, candidates ----
    {
        const int e0 = tid * 4;
        float a1v[4][4], a2v[4][4]; int a1s[4][4];
        #pragma unroll
        for (int w = 0; w < 4; ++w) {
            *(float4*)a1v[w] = *(float4*)&v1s[w * 1024 + e0];
            *(int4*)a1s[w]   = *(int4*)&s1s[w * 1024 + e0];
            *(float4*)a2v[w] = *(float4*)&v2s[w * 1024 + e0];
        }
        float relu4[4];
        const int b = bTile + (e0 >> 3);
        #pragma unroll
        for (int k = 0; k < 4; ++k) {
            float m1 = -3.4e38f, m2 = -3.4e38f; int s1 = 0;
            #pragma unroll
            for (int w = 0; w < 4; ++w) {
                float a1 = a1v[w][k], a2 = a2v[w][k];
                if (a1 > m1) { m2 = fmaxf(m1, fmaxf(m2, a2)); m1 = a1; s1 = a1s[w][k]; }
                else { m2 = fmaxf(m2, a1); }
            }
            relu4[k] = fmaxf(m1, 0.f);
            const int h = hBase + ((e0 + k) & 7);
            atomicAdd(&g_cnt[h * NS + s1], 1);
            if (m1 - m2 < CAND_THR) {
                int idx = atomicAdd(&g_candCount, 1);
                if (idx < CAND_CAP) { int4 cd; cd.x = b; cd.y = h; cd.z = s1; cd.w = 0; g_cand[idx] = cd; }
            }
        }
        *(float4*)&g_hTop[(size_t)b * NH + hBase + (e0 & 7)] = *(float4*)relu4;
    }
}

// ---------------- exact fp32 fixup of near-tie argmax decisions ----------------
__global__ void fixup_kernel(const float* __restrict__ x, const float* __restrict__ W0,
                             const float* __restrict__ b0) {
    __shared__ float part[256];
    __shared__ float zrow[NS];
    int cnt = g_candCount; if (cnt > CAND_CAP) cnt = CAND_CAP;
    const int t = threadIdx.x, s = t >> 3, p = t & 7;
    for (int i = blockIdx.x; i < cnt; i += gridDim.x) {
        int4 cd = g_cand[i];
        const float* xr = x + cd.x * ND;
        const float* wr = W0 + (size_t)s * (NH * ND) + cd.y * ND;
        float acc = 0.f;
        #pragma unroll 8
        for (int d = p * 32; d < p * 32 + 32; ++d) acc = fmaf(xr[d], wr[d], acc);
        part[t] = acc;
        __syncthreads();
        if (p == 0) {
            float z = part[t];
            #pragma unroll
            for (int j = 1; j < 8; ++j) z += part[t + j];
            zrow[s] = z + b0[s * NH + cd.y];
        }
        __syncthreads();
        if (t == 0) {
            float m = zrow[0]; int sm_ = 0;
            #pragma unroll
            for (int ss = 1; ss < NS; ++ss)
                if (zrow[ss] > m) { m = zrow[ss]; sm_ = ss; }
            if (sm_ != cd.z) {
                atomicSub(&g_cnt[cd.y * NS + cd.z], 1);
                atomicAdd(&g_cnt[cd.y * NS + sm_], 1);
            }
        }
        __syncthreads();
    }
}

// ---------------- topKweights via histogram-weighted W0 ----------------
__global__ void topkw_kernel(const float* __restrict__ W0, float* __restrict__ out) {
    const int h = blockIdx.x;
    const int d = threadIdx.x;
    __shared__ float cs[NS];
    if (d < NS) cs[d] = (float)g_cnt[h * NS + d];
    __syncthreads();
    float acc = 0.f;
    #pragma unroll
    for (int s = 0; s < NS; ++s)
        acc = fmaf(cs[s], W0[(size_t)s * (NH * ND) + h * ND + d], acc);
    out[2 + NB * NC + h * ND + d] = acc * (1.f / (float)NB) + g_meanUpd[d] * (0.001f / (float)NB);
}

// ---------------- logits + log_softmax + per-row loss/correct ----------------
__device__ __forceinline__ unsigned ord_encode(float f) {
    unsigned i = __float_as_uint(f);
    return (i & 0x80000000u) ? ~i : (i | 0x80000000u);
}
__device__ __forceinline__ float ord_decode(unsigned u) {
    unsigned i = (u & 0x80000000u) ? (u & 0x7FFFFFFFu) : ~u;
    return __uint_as_float(i);
}

__global__ __launch_bounds__(128)
void out_kernel(const float* __restrict__ W1, const float* __restrict__ b1,
                const int* __restrict__ y, float* __restrict__ out) {
    __shared__ float sh[4][NH];
    __shared__ float w1s[NC][33];
    __shared__ unsigned long long redp[NC];
    __shared__ float redf[NC];
    const int bBase = blockIdx.x * 4;
    const int c = threadIdx.x;

    #pragma unroll
    for (int bi = 0; bi < 4; ++bi)
        #pragma unroll
        for (int k = 0; k < 4; ++k)
            sh[bi][c + k * NC] = g_hTop[(size_t)(bBase + bi) * NH + c + k * NC];

    float acc[4];
    float biasv = b1[c];
    #pragma unroll
    for (int bi = 0; bi < 4; ++bi) acc[bi] = biasv;

    for (int hc = 0; hc < NH / 32; ++hc) {
        __syncthreads();
        #pragma unroll
        for (int k = 0; k < 32; ++k) {
            int e = c + k * NC;
            int cc = e >> 5, jj = e & 31;
            w1s[cc][jj] = W1[cc * NH + hc * 32 + jj];
        }
        __syncthreads();
        #pragma unroll
        for (int j = 0; j < 32; ++j) {
            float w = w1s[c][j];
            int hh = hc * 32 + j;
            #pragma unroll
            for (int bi = 0; bi < 4; ++bi)
                acc[bi] = fmaf(sh[bi][hh], w, acc[bi]);
        }
    }
    __syncthreads();

    for (int bi = 0; bi < 4; ++bi) {
        const int b = bBase + bi;
        const float lg = acc[bi];
        unsigned long long pk =
            ((unsigned long long)ord_encode(lg) << 32) | (unsigned)(NC - 1 - c);
        redp[c] = pk;
        __syncthreads();
        for (int off = NC / 2; off > 0; off >>= 1) {
            if (c < off) { if (redp[c + off] > redp[c]) redp[c] = redp[c + off]; }
            __syncthreads();
        }
        unsigned long long pmax = redp[0];
        float m = ord_decode((unsigned)(pmax >> 32));
        int cmax = NC - 1 - (int)(pmax & 0xFFFFFFFFu);
        __syncthreads();
        redf[c] = expf(lg - m);
        __syncthreads();
        for (int off = NC / 2; off > 0; off >>= 1) {
            if (c < off) redf[c] += redf[c + off];
            __syncthreads();
        }
        float lse = logf(redf[0]);
        float lp = lg - m - lse;
        out[2 + b * NC + c] = lp;
        int yb = y[b];
        if (c == yb) g_lossRow[b] = -lp;
        if (c == 0)  g_corrRow[b] = (cmax == yb) ? 1.f : 0.f;
        __syncthreads();
    }
}

__global__ void finalize_kernel(float* out) {
    __shared__ float sl[NB], sc[NB];
    int t = threadIdx.x;
    sl[t] = g_lossRow[t];
    sc[t] = g_corrRow[t];
    __syncthreads();
    for (int off = NB / 2; off > 0; off >>= 1) {
        if (t < off) { sl[t] += sl[t + off]; sc[t] += sc[t + off]; }
        __syncthreads();
    }
    if (t == 0) { out[0] = sl[0] / (float)NB; out[1] = sc[0] / (float)NB; }
}

// ---------------- launcher ----------------
extern "C" void kernel_launch(void* const* d_in, const int* in_sizes, int n_in,
                              void* d_out, int out_size) {
    const float* x  = (const float*)d_in[0];
    const int*   y  = (const int*)d_in[1];
    const float* W0 = (const float*)d_in[2];
    const float* b0 = (const float*)d_in[3];
    const float* W1 = (const float*)d_in[4];
    const float* b1 = (const float*)d_in[5];
    float* out = (float*)d_out;

    convx_kernel<<<256, 256>>>(x);
    convw_kernel<<<8192, 256>>>(W0);
    meanupd_kernel<<<16, 256>>>(x);
    gemm_mma_kernel<<<dim3(64, 4), 256>>>(b0);
    fixup_kernel<<<64, 256>>>(x, W0, b0);
    topkw_kernel<<<NH, ND>>>(W0, out);
    out_kernel<<<NB / 4, NC>>>(W1, b1, y, out);
    finalize_kernel<<<1, NB>>>(out);
}

// round 4
// speedup vs baseline: 2.5633x; 1.3389x over previous
#include <cuda_runtime.h>
#include <cuda_bf16.h>
#include <cstdint>

#define NB 512
#define NS 32
#define NH 512
#define ND 256
#define NC 128
#define KEXT 768          // 3 x 256 (bf16x3 emulation folded into K)
#define CAND_CAP 16384
#define CAND_THR 3e-5f

// ---------------- device scratch (static, no allocation) ----------------
__device__ __nv_bfloat16 g_Aext[NB * KEXT];                 // [b][768] = [xh|xh|xl]
__device__ __nv_bfloat16 g_Bext[(size_t)NS * NH * KEXT];    // [s*512+h][768] = [wh|wl|wh]
__device__ float g_hTop[NB * NH];                           // relu(max_s z) [b][h]
__device__ int   g_cnt[NH * NS];                            // argmax histogram
__device__ float g_muPart[16][ND];                          // meanUpd partials
__device__ float g_lossRow[NB];
__device__ float g_corrRow[NB];
__device__ int   g_candCount;
__device__ int4  g_cand[CAND_CAP];                          // (b, h, s1, 0)

// ---------------- PTX helpers (plain sm_100 safe) ----------------
__device__ __forceinline__ uint32_t smem_u32(const void* p) {
    uint32_t a;
    asm("{ .reg .u64 t; cvta.to.shared.u64 t, %1; cvt.u32.u64 %0, t; }" : "=r"(a) : "l"(p));
    return a;
}
#define CP_ASYNC16(dst, src) \
    asm volatile("cp.async.cg.shared.global [%0], [%1], 16;" :: "r"(dst), "l"(src) : "memory")
#define CP_COMMIT() asm volatile("cp.async.commit_group;" ::: "memory")
#define CP_WAIT_GROUP(n) asm volatile("cp.async.wait_group %0;" :: "n"(n) : "memory")

__device__ __forceinline__ void ldsm4(uint32_t* r, uint32_t addr) {
    asm volatile("ldmatrix.sync.aligned.m8n8.x4.shared.b16 {%0,%1,%2,%3}, [%4];"
        : "=r"(r[0]), "=r"(r[1]), "=r"(r[2]), "=r"(r[3]) : "r"(addr));
}
__device__ __forceinline__ void mma16816(float* c, const uint32_t* a, const uint32_t* b) {
    asm volatile("mma.sync.aligned.m16n8k16.row.col.f32.bf16.bf16.f32 "
        "{%0,%1,%2,%3}, {%4,%5,%6,%7}, {%8,%9}, {%0,%1,%2,%3};"
        : "+f"(c[0]), "+f"(c[1]), "+f"(c[2]), "+f"(c[3])
        : "r"(a[0]), "r"(a[1]), "r"(a[2]), "r"(a[3]), "r"(b[0]), "r"(b[1]));
}

// swizzled 16B-slot offset inside a [rows][64B] tile (4 slots/row)
__device__ __forceinline__ uint32_t phys64(int row, int c) {
    return (uint32_t)(row * 64 + (((c ^ (row >> 1)) & 3) << 4));
}

// ---------------- bf16 split helpers ----------------
__device__ __forceinline__ void split2(float a, float b, uint32_t& hi, uint32_t& lo) {
    __nv_bfloat16 h0 = __float2bfloat16_rn(a);
    __nv_bfloat16 h1 = __float2bfloat16_rn(b);
    __nv_bfloat16 l0 = __float2bfloat16_rn(a - __bfloat162float(h0));
    __nv_bfloat16 l1 = __float2bfloat16_rn(b - __bfloat162float(h1));
    __nv_bfloat162 hh; hh.x = h0; hh.y = h1;
    __nv_bfloat162 ll; ll.x = l0; ll.y = l1;
    hi = *(uint32_t*)&hh; lo = *(uint32_t*)&ll;
}

// ---------------- convert x -> A_ext (+ meanUpd partials) ----------------
__global__ void convx_kernel(const float* __restrict__ x) {
    int idx = blockIdx.x * 256 + threadIdx.x;   // 0..32767 float4s
    float4 v = ((const float4*)x)[idx];
    int b = idx >> 6, q = idx & 63, d = q * 4;
    uint32_t hA, lA, hB, lB;
    split2(v.x, v.y, hA, lA);
    split2(v.z, v.w, hB, lB);
    uint32_t* base = (uint32_t*)(g_Aext + b * KEXT);
    uint2 hi2; hi2.x = hA; hi2.y = hB;
    uint2 lo2; lo2.x = lA; lo2.y = lB;
    *(uint2*)(base + (d >> 1)) = hi2;
    *(uint2*)(base + ((256 + d) >> 1)) = hi2;
    *(uint2*)(base + ((512 + d) >> 1)) = lo2;
    if (blockIdx.x < 16) {
        int k = blockIdx.x, dd = threadIdx.x;
        float acc = 0.f;
        #pragma unroll 8
        for (int bb = 0; bb < 32; ++bb) {
            float xv = x[(k * 32 + bb) * ND + dd];
            acc += (xv > 0.f ? 1.f : 0.f) - (xv < 0.f ? 1.f : 0.f);
        }
        g_muPart[k][dd] = acc;
    }
}

// ---------------- W0 -> B_ext (+ zero scratch piggyback) ----------------
__global__ void convw_kernel(const float* __restrict__ W0) {
    int bid = blockIdx.x, tid = threadIdx.x;
    if (bid < 16) {
        #pragma unroll
        for (int j = 0; j < 4; ++j) g_cnt[bid * 1024 + j * 256 + tid] = 0;
    } else if (bid == 16 && tid == 0) {
        g_candCount = 0;
    }
    int idx = bid * 256 + tid;                  // 0..1048575 float4s
    float4 v = ((const float4*)W0)[idx];
    int row = idx >> 6, q = idx & 63, d = q * 4;   // row = s*512+h
    uint32_t hA, lA, hB, lB;
    split2(v.x, v.y, hA, lA);
    split2(v.z, v.w, hB, lB);
    uint32_t* base = (uint32_t*)(g_Bext + (size_t)row * KEXT);
    uint2 hi2; hi2.x = hA; hi2.y = hB;
    uint2 lo2; lo2.x = lA; lo2.y = lB;
    *(uint2*)(base + (d >> 1)) = hi2;
    *(uint2*)(base + ((256 + d) >> 1)) = lo2;
    *(uint2*)(base + ((512 + d) >> 1)) = hi2;
}

// ---------------- mma.sync GEMM + fused max/argmax epilogue ----------------
// grid (64 h-tiles, 4 b-tiles), 256 threads (8 warps: 2 wb x 4 wn).
// CTA tile 128 b x 256 n, n = s*8 + hl. Warp tile 64x64.
// K: 24 chunks of 32, 4-stage cp.async ring (24KB/stage, 96KB dynamic).
#define NCHUNK 24
#define STAGE_B 24576

__global__ __launch_bounds__(256, 1)
void gemm_mma_kernel(const float* __restrict__ b0) {
    extern __shared__ char sm[];
    const uint32_t sbase = smem_u32(sm);
    const int tid = threadIdx.x;
    const int lane = tid & 31, warp = tid >> 5;
    const int wb = warp >> 2, wn = warp & 3;
    const int hBase = blockIdx.x * 8;
    const int bTile = blockIdx.y * 128;

    // ---- producer per-thread mapping: 2 A slots + 4 B slots per chunk ----
    const int prow = tid >> 2, pc = tid & 3;
    const uint32_t dA0 = phys64(prow, pc), dA1 = phys64(prow + 64, pc);
    uint32_t dB[4];
    const __nv_bfloat16* srcB[4];
    #pragma unroll
    for (int r = 0; r < 4; ++r) {
        int n = prow + 64 * r;
        dB[r] = 8192 + phys64(n, pc);
        srcB[r] = g_Bext + (size_t)((n >> 3) * NH + hBase + (n & 7)) * KEXT + pc * 8;
    }
    const __nv_bfloat16* srcA0 = g_Aext + (size_t)(bTile + prow) * KEXT + pc * 8;
    const __nv_bfloat16* srcA1 = g_Aext + (size_t)(bTile + prow + 64) * KEXT + pc * 8;

    // ---- ldsm per-thread offsets (stage-relative), both k-halves ----
    uint32_t aOff[2][4], bOff[2][4];
    {
        const int arow = lane & 15, asl = lane >> 4;
        #pragma unroll
        for (int mb = 0; mb < 4; ++mb) {
            int row = wb * 64 + mb * 16 + arow;
            aOff[0][mb] = phys64(row, asl);
            aOff[1][mb] = phys64(row, 2 + asl);
        }
        const int brow = ((lane >> 4) << 3) + (lane & 7), bsl = (lane >> 3) & 1;
        #pragma unroll
        for (int jb = 0; jb < 4; ++jb) {
            int n = wn * 64 + jb * 16 + brow;
            bOff[0][jb] = 8192 + phys64(n, bsl);
            bOff[1][jb] = 8192 + phys64(n, 2 + bsl);
        }
    }

    float acc[4][8][4];
    #pragma unroll
    for (int mb = 0; mb < 4; ++mb)
        #pragma unroll
        for (int nb = 0; nb < 8; ++nb)
            #pragma unroll
            for (int q = 0; q < 4; ++q) acc[mb][nb][q] = 0.f;

    // ---- prologue: 3 chunks in flight ----
    #pragma unroll
    for (int p = 0; p < 3; ++p) {
        uint32_t st = sbase + p * STAGE_B;
        const int off = p * 32;
        CP_ASYNC16(st + dA0, srcA0 + off);
        CP_ASYNC16(st + dA1, srcA1 + off);
        #pragma unroll
        for (int r = 0; r < 4; ++r) CP_ASYNC16(st + dB[r], srcB[r] + off);
        CP_COMMIT();
    }

    // ---- mainloop ----
    for (int c = 0; c < NCHUNK; ++c) {
        CP_WAIT_GROUP(2);
        __syncthreads();
        if (c + 3 < NCHUNK) {
            uint32_t st = sbase + ((c + 3) & 3) * STAGE_B;
            const int off = (c + 3) * 32;
            CP_ASYNC16(st + dA0, srcA0 + off);
            CP_ASYNC16(st + dA1, srcA1 + off);
            #pragma unroll
            for (int r = 0; r < 4; ++r) CP_ASYNC16(st + dB[r], srcB[r] + off);
        }
        CP_COMMIT();

        const uint32_t base = sbase + (c & 3) * STAGE_B;
        uint32_t af[2][4][4], bf[2][4][4];
        #pragma unroll
        for (int kh = 0; kh < 2; ++kh) {
            #pragma unroll
            for (int mb = 0; mb < 4; ++mb) ldsm4(af[kh][mb], base + aOff[kh][mb]);
            #pragma unroll
            for (int jb = 0; jb < 4; ++jb) ldsm4(bf[kh][jb], base + bOff[kh][jb]);
        }
        #pragma unroll
        for (int kh = 0; kh < 2; ++kh)
            #pragma unroll
            for (int mb = 0; mb < 4; ++mb)
                #pragma unroll
                for (int jb = 0; jb < 4; ++jb) {
                    mma16816(acc[mb][jb * 2],     af[kh][mb], &bf[kh][jb][0]);
                    mma16816(acc[mb][jb * 2 + 1], af[kh][mb], &bf[kh][jb][2]);
                }
    }
    __syncthreads();

    // ---- epilogue phase 1: per-warp top-2 over this warp's 8 s ----
    float* v1s = (float*)sm;               // [4 wn][1024]
    int*   s1s = (int*)(sm + 16384);
    float* v2s = (float*)(sm + 32768);

    float biasv[8][2];
    #pragma unroll
    for (int nb = 0; nb < 8; ++nb)
        #pragma unroll
        for (int q = 0; q < 2; ++q)
            biasv[nb][q] = __ldg(&b0[(wn * 8 + nb) * NH + hBase + (lane & 3) * 2 + q]);

    #pragma unroll
    for (int mb = 0; mb < 4; ++mb)
        #pragma unroll
        for (int half = 0; half < 2; ++half)
            #pragma unroll
            for (int q = 0; q < 2; ++q) {
                float m1 = -3.4e38f, m2 = -3.4e38f; int s1 = 0;
                #pragma unroll
                for (int nb = 0; nb < 8; ++nb) {
                    float v = acc[mb][nb][half * 2 + q] + biasv[nb][q];
                    if (v > m1) { m2 = m1; m1 = v; s1 = wn * 8 + nb; }
                    else if (v > m2) m2 = v;
                }
                int row = wb * 64 + mb * 16 + half * 8 + (lane >> 2);
                int hl = (lane & 3) * 2 + q;
                int e = row * 8 + hl;
                v1s[wn * 1024 + e] = m1;
                s1s[wn * 1024 + e] = s1;
                v2s[wn * 1024 + e] = m2;
            }
    __syncthreads();

    // ---- epilogue phase 2: cross-warp combine, write hTop, hist, candidates ----
    {
        const int e0 = tid * 4;
        float a1v[4][4], a2v[4][4]; int a1s[4][4];
        #pragma unroll
        for (int w = 0; w < 4; ++w) {
            *(float4*)a1v[w] = *(float4*)&v1s[w * 1024 + e0];
            *(int4*)a1s[w]   = *(int4*)&s1s[w * 1024 + e0];
            *(float4*)a2v[w] = *(float4*)&v2s[w * 1024 + e0];
        }
        float relu4[4];
        const int b = bTile + (e0 >> 3);
        #pragma unroll
        for (int k = 0; k < 4; ++k) {
            float m1 = -3.4e38f, m2 = -3.4e38f; int s1 = 0;
            #pragma unroll
            for (int w = 0; w < 4; ++w) {
                float a1 = a1v[w][k], a2 = a2v[w][k];
                if (a1 > m1) { m2 = fmaxf(m1, fmaxf(m2, a2)); m1 = a1; s1 = a1s[w][k]; }
                else { m2 = fmaxf(m2, a1); }
            }
            relu4[k] = fmaxf(m1, 0.f);
            const int h = hBase + ((e0 + k) & 7);
            atomicAdd(&g_cnt[h * NS + s1], 1);
            if (m1 - m2 < CAND_THR) {
                int idx = atomicAdd(&g_candCount, 1);
                if (idx < CAND_CAP) { int4 cd; cd.x = b; cd.y = h; cd.z = s1; cd.w = 0; g_cand[idx] = cd; }
            }
        }
        *(float4*)&g_hTop[(size_t)b * NH + hBase + (e0 & 7)] = *(float4*)relu4;
    }
}

// ---------------- exact fp32 fixup of near-tie argmax decisions ----------------
__global__ void fixup_kernel(const float* __restrict__ x, const float* __restrict__ W0,
                             const float* __restrict__ b0) {
    __shared__ float part[256];
    __shared__ float zrow[NS];
    int cnt = g_candCount; if (cnt > CAND_CAP) cnt = CAND_CAP;
    const int t = threadIdx.x, s = t >> 3, p = t & 7;
    for (int i = blockIdx.x; i < cnt; i += gridDim.x) {
        int4 cd = g_cand[i];
        const float* xr = x + cd.x * ND;
        const float* wr = W0 + (size_t)s * (NH * ND) + cd.y * ND;
        float acc = 0.f;
        #pragma unroll 8
        for (int d = p * 32; d < p * 32 + 32; ++d) acc = fmaf(xr[d], wr[d], acc);
        part[t] = acc;
        __syncthreads();
        if (p == 0) {
            float z = part[t];
            #pragma unroll
            for (int j = 1; j < 8; ++j) z += part[t + j];
            zrow[s] = z + b0[s * NH + cd.y];
        }
        __syncthreads();
        if (t == 0) {
            float m = zrow[0]; int sm_ = 0;
            #pragma unroll
            for (int ss = 1; ss < NS; ++ss)
                if (zrow[ss] > m) { m = zrow[ss]; sm_ = ss; }
            if (sm_ != cd.z) {
                atomicSub(&g_cnt[cd.y * NS + cd.z], 1);
                atomicAdd(&g_cnt[cd.y * NS + sm_], 1);
            }
        }
        __syncthreads();
    }
}

// ---------------- topKweights via histogram-weighted W0 ----------------
__global__ void topkw_kernel(const float* __restrict__ W0, float* __restrict__ out) {
    const int h = blockIdx.x;
    const int d = threadIdx.x;
    __shared__ float cs[NS];
    if (d < NS) cs[d] = (float)g_cnt[h * NS + d];
    __syncthreads();
    float mu = 0.f;
    #pragma unroll
    for (int k = 0; k < 16; ++k) mu += g_muPart[k][d];
    float acc = 0.f;
    #pragma unroll
    for (int s = 0; s < NS; ++s)
        acc = fmaf(cs[s], W0[(size_t)s * (NH * ND) + h * ND + d], acc);
    out[2 + NB * NC + h * ND + d] = acc * (1.f / (float)NB) + mu * (0.001f / (float)NB);
}

// ---------------- logits + log_softmax + per-row loss/correct ----------------
__device__ __forceinline__ unsigned ord_encode(float f) {
    unsigned i = __float_as_uint(f);
    return (i & 0x80000000u) ? ~i : (i | 0x80000000u);
}
__device__ __forceinline__ float ord_decode(unsigned u) {
    unsigned i = (u & 0x80000000u) ? (u & 0x7FFFFFFFu) : ~u;
    return __uint_as_float(i);
}

__global__ __launch_bounds__(128)
void out_kernel(const float* __restrict__ W1, const float* __restrict__ b1,
                const int* __restrict__ y, float* __restrict__ out) {
    __shared__ float sh[4][NH];
    __shared__ float w1s[NC][33];
    __shared__ unsigned long long redp[NC];
    __shared__ float redf[NC];
    const int bBase = blockIdx.x * 4;
    const int c = threadIdx.x;

    #pragma unroll
    for (int bi = 0; bi < 4; ++bi)
        #pragma unroll
        for (int k = 0; k < 4; ++k)
            sh[bi][c + k * NC] = g_hTop[(size_t)(bBase + bi) * NH + c + k * NC];

    float acc[4];
    float biasv = b1[c];
    #pragma unroll
    for (int bi = 0; bi < 4; ++bi) acc[bi] = biasv;

    for (int hc = 0; hc < NH / 32; ++hc) {
        __syncthreads();
        #pragma unroll
        for (int k = 0; k < 32; ++k) {
            int e = c + k * NC;
            int cc = e >> 5, jj = e & 31;
            w1s[cc][jj] = W1[cc * NH + hc * 32 + jj];
        }
        __syncthreads();
        #pragma unroll
        for (int j = 0; j < 32; ++j) {
            float w = w1s[c][j];
            int hh = hc * 32 + j;
            #pragma unroll
            for (int bi = 0; bi < 4; ++bi)
                acc[bi] = fmaf(sh[bi][hh], w, acc[bi]);
        }
    }
    __syncthreads();

    for (int bi = 0; bi < 4; ++bi) {
        const int b = bBase + bi;
        const float lg = acc[bi];
        unsigned long long pk =
            ((unsigned long long)ord_encode(lg) << 32) | (unsigned)(NC - 1 - c);
        redp[c] = pk;
        __syncthreads();
        for (int off = NC / 2; off > 0; off >>= 1) {
            if (c < off) { if (redp[c + off] > redp[c]) redp[c] = redp[c + off]; }
            __syncthreads();
        }
        unsigned long long pmax = redp[0];
        float m = ord_decode((unsigned)(pmax >> 32));
        int cmax = NC - 1 - (int)(pmax & 0xFFFFFFFFu);
        __syncthreads();
        redf[c] = expf(lg - m);
        __syncthreads();
        for (int off = NC / 2; off > 0; off >>= 1) {
            if (c < off) redf[c] += redf[c + off];
            __syncthreads();
        }
        float lse = logf(redf[0]);
        float lp = lg - m - lse;
        out[2 + b * NC + c] = lp;
        int yb = y[b];
        if (c == yb) g_lossRow[b] = -lp;
        if (c == 0)  g_corrRow[b] = (cmax == yb) ? 1.f : 0.f;
        __syncthreads();
    }
}

__global__ void finalize_kernel(float* out) {
    __shared__ float sl[NB], sc[NB];
    int t = threadIdx.x;
    sl[t] = g_lossRow[t];
    sc[t] = g_corrRow[t];
    __syncthreads();
    for (int off = NB / 2; off > 0; off >>= 1) {
        if (t < off) { sl[t] += sl[t + off]; sc[t] += sc[t + off]; }
        __syncthreads();
    }
    if (t == 0) { out[0] = sl[0] / (float)NB; out[1] = sc[0] / (float)NB; }
}

// ---------------- launcher ----------------
extern "C" void kernel_launch(void* const* d_in, const int* in_sizes, int n_in,
                              void* d_out, int out_size) {
    const float* x  = (const float*)d_in[0];
    const int*   y  = (const int*)d_in[1];
    const float* W0 = (const float*)d_in[2];
    const float* b0 = (const float*)d_in[3];
    const float* W1 = (const float*)d_in[4];
    const float* b1 = (const float*)d_in[5];
    float* out = (float*)d_out;

    static cudaStream_t s1;
    static cudaEvent_t eG, eO;
    static bool inited = false;
    if (!inited) {
        cudaStreamCreateWithFlags(&s1, cudaStreamNonBlocking);
        cudaEventCreateWithFlags(&eG, cudaEventDisableTiming);
        cudaEventCreateWithFlags(&eO, cudaEventDisableTiming);
        cudaFuncSetAttribute(gemm_mma_kernel,
                             cudaFuncAttributeMaxDynamicSharedMemorySize, 4 * STAGE_B);
        inited = true;
    }

    convx_kernel<<<128, 256>>>(x);
    convw_kernel<<<4096, 256>>>(W0);
    gemm_mma_kernel<<<dim3(64, 4), 256, 4 * STAGE_B>>>(b0);
    cudaEventRecord(eG, 0);

    // side stream: output head (depends only on g_hTop)
    cudaStreamWaitEvent(s1, eG, 0);
    out_kernel<<<NB / 4, NC, 0, s1>>>(W1, b1, y, out);
    finalize_kernel<<<1, NB, 0, s1>>>(out);
    cudaEventRecord(eO, s1);

    // main stream: histogram correction + topKweights
    fixup_kernel<<<64, 256>>>(x, W0, b0);
    topkw_kernel<<<NH, ND>>>(W0, out);
    cudaStreamWaitEvent(0, eO, 0);
}

// round 6
// speedup vs baseline: 2.7619x; 1.0775x over previous
#include <cuda_runtime.h>
#include <cuda_bf16.h>
#include <cstdint>

#define NB 512
#define NS 32
#define NH 512
#define ND 256
#define NC 128
#define KEXT 768          // 3 x 256 (bf16x3 emulation folded into K)
#define CAND_CAP 16384
#define CAND_THR 3e-5f

// ---------------- device scratch (static, no allocation) ----------------
__device__ __nv_bfloat16 g_Aext[NB * KEXT];                 // [b][768] = [xh|xh|xl]
__device__ __nv_bfloat16 g_Bext[(size_t)NS * NH * KEXT];    // [s*512+h][768] = [wh|wl|wh]
__device__ float g_hTop[NB * NH];                           // relu(max_s z) [b][h]
__device__ int   g_cnt[NH * NS];                            // argmax histogram
__device__ float g_muPart[16][ND];                          // meanUpd partials
__device__ float g_lossRow[NB];
__device__ float g_corrRow[NB];
__device__ int   g_candCount;
__device__ int4  g_cand[CAND_CAP];                          // (b, h, s1, 0)

// ---------------- PTX helpers (plain sm_100 safe) ----------------
__device__ __forceinline__ uint32_t smem_u32(const void* p) {
    uint32_t a;
    asm("{ .reg .u64 t; cvta.to.shared.u64 t, %1; cvt.u32.u64 %0, t; }" : "=r"(a) : "l"(p));
    return a;
}
#define CP_ASYNC16(dst, src) \
    asm volatile("cp.async.cg.shared.global [%0], [%1], 16;" :: "r"(dst), "l"(src) : "memory")
#define CP_COMMIT() asm volatile("cp.async.commit_group;" ::: "memory")
#define CP_WAIT_GROUP(n) asm volatile("cp.async.wait_group %0;" :: "n"(n) : "memory")

__device__ __forceinline__ void ldsm4(uint32_t* r, uint32_t addr) {
    asm volatile("ldmatrix.sync.aligned.m8n8.x4.shared.b16 {%0,%1,%2,%3}, [%4];"
        : "=r"(r[0]), "=r"(r[1]), "=r"(r[2]), "=r"(r[3]) : "r"(addr));
}
__device__ __forceinline__ void mma16816(float* c, const uint32_t* a, const uint32_t* b) {
    asm volatile("mma.sync.aligned.m16n8k16.row.col.f32.bf16.bf16.f32 "
        "{%0,%1,%2,%3}, {%4,%5,%6,%7}, {%8,%9}, {%0,%1,%2,%3};"
        : "+f"(c[0]), "+f"(c[1]), "+f"(c[2]), "+f"(c[3])
        : "r"(a[0]), "r"(a[1]), "r"(a[2]), "r"(a[3]), "r"(b[0]), "r"(b[1]));
}

// swizzled 16B-slot offset inside a [rows][64B] tile (4 slots/row)
__device__ __forceinline__ uint32_t phys64(int row, int c) {
    return (uint32_t)(row * 64 + (((c ^ (row >> 1)) & 3) << 4));
}

// ---------------- bf16 split helpers ----------------
__device__ __forceinline__ void split2(float a, float b, uint32_t& hi, uint32_t& lo) {
    __nv_bfloat16 h0 = __float2bfloat16_rn(a);
    __nv_bfloat16 h1 = __float2bfloat16_rn(b);
    __nv_bfloat16 l0 = __float2bfloat16_rn(a - __bfloat162float(h0));
    __nv_bfloat16 l1 = __float2bfloat16_rn(b - __bfloat162float(h1));
    __nv_bfloat162 hh; hh.x = h0; hh.y = h1;
    __nv_bfloat162 ll; ll.x = l0; ll.y = l1;
    hi = *(uint32_t*)&hh; lo = *(uint32_t*)&ll;
}

// ---------------- convert x -> A_ext (+ meanUpd partials) ----------------
__global__ void convx_kernel(const float* __restrict__ x) {
    int idx = blockIdx.x * 256 + threadIdx.x;   // 0..32767 float4s
    float4 v = ((const float4*)x)[idx];
    int b = idx >> 6, q = idx & 63, d = q * 4;
    uint32_t hA, lA, hB, lB;
    split2(v.x, v.y, hA, lA);
    split2(v.z, v.w, hB, lB);
    uint32_t* base = (uint32_t*)(g_Aext + b * KEXT);
    uint2 hi2; hi2.x = hA; hi2.y = hB;
    uint2 lo2; lo2.x = lA; lo2.y = lB;
    *(uint2*)(base + (d >> 1)) = hi2;
    *(uint2*)(base + ((256 + d) >> 1)) = hi2;
    *(uint2*)(base + ((512 + d) >> 1)) = lo2;
    if (blockIdx.x < 16) {
        int k = blockIdx.x, dd = threadIdx.x;
        float acc = 0.f;
        #pragma unroll 8
        for (int bb = 0; bb < 32; ++bb) {
            float xv = x[(k * 32 + bb) * ND + dd];
            acc += (xv > 0.f ? 1.f : 0.f) - (xv < 0.f ? 1.f : 0.f);
        }
        g_muPart[k][dd] = acc;
    }
}

// ---------------- W0 -> B_ext (+ zero scratch piggyback) ----------------
__global__ void convw_kernel(const float* __restrict__ W0) {
    int bid = blockIdx.x, tid = threadIdx.x;
    if (bid < 16) {
        #pragma unroll
        for (int j = 0; j < 4; ++j) g_cnt[bid * 1024 + j * 256 + tid] = 0;
    } else if (bid == 16 && tid == 0) {
        g_candCount = 0;
    }
    int idx = bid * 256 + tid;                  // 0..1048575 float4s
    float4 v = ((const float4*)W0)[idx];
    int row = idx >> 6, q = idx & 63, d = q * 4;   // row = s*512+h
    uint32_t hA, lA, hB, lB;
    split2(v.x, v.y, hA, lA);
    split2(v.z, v.w, hB, lB);
    uint32_t* base = (uint32_t*)(g_Bext + (size_t)row * KEXT);
    uint2 hi2; hi2.x = hA; hi2.y = hB;
    uint2 lo2; lo2.x = lA; lo2.y = lB;
    *(uint2*)(base + (d >> 1)) = hi2;
    *(uint2*)(base + ((256 + d) >> 1)) = lo2;
    *(uint2*)(base + ((512 + d) >> 1)) = hi2;
}

// ---------------- mma.sync GEMM + fused max/argmax epilogue ----------------
#define NCHUNK 24
#define STAGE_B 24576

__global__ __launch_bounds__(256, 1)
void gemm_mma_kernel(const float* __restrict__ b0) {
    extern __shared__ char sm[];
    const uint32_t sbase = smem_u32(sm);
    const int tid = threadIdx.x;
    const int lane = tid & 31, warp = tid >> 5;
    const int wb = warp >> 2, wn = warp & 3;
    const int hBase = blockIdx.x * 8;
    const int bTile = blockIdx.y * 128;

    const int prow = tid >> 2, pc = tid & 3;
    const uint32_t dA0 = phys64(prow, pc), dA1 = phys64(prow + 64, pc);
    uint32_t dB[4];
    const __nv_bfloat16* srcB[4];
    #pragma unroll
    for (int r = 0; r < 4; ++r) {
        int n = prow + 64 * r;
        dB[r] = 8192 + phys64(n, pc);
        srcB[r] = g_Bext + (size_t)((n >> 3) * NH + hBase + (n & 7)) * KEXT + pc * 8;
    }
    const __nv_bfloat16* srcA0 = g_Aext + (size_t)(bTile + prow) * KEXT + pc * 8;
    const __nv_bfloat16* srcA1 = g_Aext + (size_t)(bTile + prow + 64) * KEXT + pc * 8;

    uint32_t aOff[2][4], bOff[2][4];
    {
        const int arow = lane & 15, asl = lane >> 4;
        #pragma unroll
        for (int mb = 0; mb < 4; ++mb) {
            int row = wb * 64 + mb * 16 + arow;
            aOff[0][mb] = phys64(row, asl);
            aOff[1][mb] = phys64(row, 2 + asl);
        }
        const int brow = ((lane >> 4) << 3) + (lane & 7), bsl = (lane >> 3) & 1;
        #pragma unroll
        for (int jb = 0; jb < 4; ++jb) {
            int n = wn * 64 + jb * 16 + brow;
            bOff[0][jb] = 8192 + phys64(n, bsl);
            bOff[1][jb] = 8192 + phys64(n, 2 + bsl);
        }
    }

    float acc[4][8][4];
    #pragma unroll
    for (int mb = 0; mb < 4; ++mb)
        #pragma unroll
        for (int nb = 0; nb < 8; ++nb)
            #pragma unroll
            for (int q = 0; q < 4; ++q) acc[mb][nb][q] = 0.f;

    #pragma unroll
    for (int p = 0; p < 3; ++p) {
        uint32_t st = sbase + p * STAGE_B;
        const int off = p * 32;
        CP_ASYNC16(st + dA0, srcA0 + off);
        CP_ASYNC16(st + dA1, srcA1 + off);
        #pragma unroll
        for (int r = 0; r < 4; ++r) CP_ASYNC16(st + dB[r], srcB[r] + off);
        CP_COMMIT();
    }

    for (int c = 0; c < NCHUNK; ++c) {
        CP_WAIT_GROUP(2);
        __syncthreads();
        if (c + 3 < NCHUNK) {
            uint32_t st = sbase + ((c + 3) & 3) * STAGE_B;
            const int off = (c + 3) * 32;
            CP_ASYNC16(st + dA0, srcA0 + off);
            CP_ASYNC16(st + dA1, srcA1 + off);
            #pragma unroll
            for (int r = 0; r < 4; ++r) CP_ASYNC16(st + dB[r], srcB[r] + off);
        }
        CP_COMMIT();

        const uint32_t base = sbase + (c & 3) * STAGE_B;
        uint32_t af[2][4][4], bf[2][4][4];
        #pragma unroll
        for (int kh = 0; kh < 2; ++kh) {
            #pragma unroll
            for (int mb = 0; mb < 4; ++mb) ldsm4(af[kh][mb], base + aOff[kh][mb]);
            #pragma unroll
            for (int jb = 0; jb < 4; ++jb) ldsm4(bf[kh][jb], base + bOff[kh][jb]);
        }
        #pragma unroll
        for (int kh = 0; kh < 2; ++kh)
            #pragma unroll
            for (int mb = 0; mb < 4; ++mb)
                #pragma unroll
                for (int jb = 0; jb < 4; ++jb) {
                    mma16816(acc[mb][jb * 2],     af[kh][mb], &bf[kh][jb][0]);
                    mma16816(acc[mb][jb * 2 + 1], af[kh][mb], &bf[kh][jb][2]);
                }
    }
    __syncthreads();

    // ---- epilogue phase 1: per-warp top-2 over this warp's 8 s ----
    float* v1s = (float*)sm;
    int*   s1s = (int*)(sm + 16384);
    float* v2s = (float*)(sm + 32768);

    float biasv[8][2];
    #pragma unroll
    for (int nb = 0; nb < 8; ++nb)
        #pragma unroll
        for (int q = 0; q < 2; ++q)
            biasv[nb][q] = __ldg(&b0[(wn * 8 + nb) * NH + hBase + (lane & 3) * 2 + q]);

    #pragma unroll
    for (int mb = 0; mb < 4; ++mb)
        #pragma unroll
        for (int half = 0; half < 2; ++half)
            #pragma unroll
            for (int q = 0; q < 2; ++q) {
                float m1 = -3.4e38f, m2 = -3.4e38f; int s1 = 0;
                #pragma unroll
                for (int nb = 0; nb < 8; ++nb) {
                    float v = acc[mb][nb][half * 2 + q] + biasv[nb][q];
                    if (v > m1) { m2 = m1; m1 = v; s1 = wn * 8 + nb; }
                    else if (v > m2) m2 = v;
                }
                int row = wb * 64 + mb * 16 + half * 8 + (lane >> 2);
                int hl = (lane & 3) * 2 + q;
                int e = row * 8 + hl;
                v1s[wn * 1024 + e] = m1;
                s1s[wn * 1024 + e] = s1;
                v2s[wn * 1024 + e] = m2;
            }
    __syncthreads();

    // ---- epilogue phase 2: combine, write hTop, hist, candidates ----
    {
        const int e0 = tid * 4;
        float a1v[4][4], a2v[4][4]; int a1s[4][4];
        #pragma unroll
        for (int w = 0; w < 4; ++w) {
            *(float4*)a1v[w] = *(float4*)&v1s[w * 1024 + e0];
            *(int4*)a1s[w]   = *(int4*)&s1s[w * 1024 + e0];
            *(float4*)a2v[w] = *(float4*)&v2s[w * 1024 + e0];
        }
        float relu4[4];
        const int b = bTile + (e0 >> 3);
        #pragma unroll
        for (int k = 0; k < 4; ++k) {
            float m1 = -3.4e38f, m2 = -3.4e38f; int s1 = 0;
            #pragma unroll
            for (int w = 0; w < 4; ++w) {
                float a1 = a1v[w][k], a2 = a2v[w][k];
                if (a1 > m1) { m2 = fmaxf(m1, fmaxf(m2, a2)); m1 = a1; s1 = a1s[w][k]; }
                else { m2 = fmaxf(m2, a1); }
            }
            relu4[k] = fmaxf(m1, 0.f);
            const int h = hBase + ((e0 + k) & 7);
            atomicAdd(&g_cnt[h * NS + s1], 1);
            if (m1 - m2 < CAND_THR) {
                int idx = atomicAdd(&g_candCount, 1);
                if (idx < CAND_CAP) { int4 cd; cd.x = b; cd.y = h; cd.z = s1; cd.w = 0; g_cand[idx] = cd; }
            }
        }
        *(float4*)&g_hTop[(size_t)b * NH + hBase + (e0 & 7)] = *(float4*)relu4;
    }
}

// ---------------- exact fp32 fixup of near-tie argmax decisions ----------------
__global__ void fixup_kernel(const float* __restrict__ x, const float* __restrict__ W0,
                             const float* __restrict__ b0) {
    __shared__ float part[256];
    __shared__ float zrow[NS];
    int cnt = g_candCount; if (cnt > CAND_CAP) cnt = CAND_CAP;
    const int t = threadIdx.x, s = t >> 3, p = t & 7;
    for (int i = blockIdx.x; i < cnt; i += gridDim.x) {
        int4 cd = g_cand[i];
        const float* xr = x + cd.x * ND;
        const float* wr = W0 + (size_t)s * (NH * ND) + cd.y * ND;
        float acc = 0.f;
        #pragma unroll 8
        for (int d = p * 32; d < p * 32 + 32; ++d) acc = fmaf(xr[d], wr[d], acc);
        part[t] = acc;
        __syncthreads();
        if (p == 0) {
            float z = part[t];
            #pragma unroll
            for (int j = 1; j < 8; ++j) z += part[t + j];
            zrow[s] = z + b0[s * NH + cd.y];
        }
        __syncthreads();
        if (t == 0) {
            float m = zrow[0]; int sm_ = 0;
            #pragma unroll
            for (int ss = 1; ss < NS; ++ss)
                if (zrow[ss] > m) { m = zrow[ss]; sm_ = ss; }
            if (sm_ != cd.z) {
                atomicSub(&g_cnt[cd.y * NS + cd.z], 1);
                atomicAdd(&g_cnt[cd.y * NS + sm_], 1);
            }
        }
        __syncthreads();
    }
}

// ---------------- topKweights via histogram-weighted W0 ----------------
__global__ void topkw_kernel(const float* __restrict__ W0, float* __restrict__ out) {
    const int h = blockIdx.x;
    const int d = threadIdx.x;
    __shared__ float cs[NS];
    if (d < NS) cs[d] = (float)g_cnt[h * NS + d];
    __syncthreads();
    float mu = 0.f;
    #pragma unroll
    for (int k = 0; k < 16; ++k) mu += g_muPart[k][d];
    float acc = 0.f;
    #pragma unroll
    for (int s = 0; s < NS; ++s)
        acc = fmaf(cs[s], W0[(size_t)s * (NH * ND) + h * ND + d], acc);
    out[2 + NB * NC + h * ND + d] = acc * (1.f / (float)NB) + mu * (0.001f / (float)NB);
}

// ---------------- output head: logits + log_softmax, warp-parallel ----------------
// grid 64 blocks x 256 threads. 8 b-rows per block.
__global__ __launch_bounds__(256)
void out_kernel(const float* __restrict__ W1, const float* __restrict__ b1,
                const int* __restrict__ y, float* __restrict__ out) {
    __shared__ float sx[8][NH];        // 16 KB
    __shared__ float w1s[32][129];     // 16.5 KB (transposed chunk [h_local][c])
    __shared__ float lg[8][NC];        // 4 KB
    const int tid = threadIdx.x;
    const int lane = tid & 31, warp = tid >> 5;
    const int bBase = blockIdx.x * 8;

    // load 8 x-rows (4096 floats contiguous)
    #pragma unroll
    for (int k = 0; k < 4; ++k)
        ((float4*)sx)[tid + k * 256] = ((const float4*)(g_hTop + (size_t)bBase * NH))[tid + k * 256];

    const int rg = warp >> 2;          // 0/1 -> rows rg*4..rg*4+3
    const int cq = warp & 3;
    const int c = cq * 32 + lane;
    float acc[4] = {0.f, 0.f, 0.f, 0.f};

    for (int ch = 0; ch < 16; ++ch) {
        __syncthreads();
        // load W1 chunk [128 c][32 h] transposed into w1s[h][c]
        #pragma unroll
        for (int k = 0; k < 4; ++k) {
            int i = tid + k * 256;              // float4 idx 0..1023
            int c2 = i >> 3, col4 = i & 7;
            float4 v = ((const float4*)W1)[c2 * (NH / 4) + ch * 8 + col4];
            w1s[col4 * 4 + 0][c2] = v.x;
            w1s[col4 * 4 + 1][c2] = v.y;
            w1s[col4 * 4 + 2][c2] = v.z;
            w1s[col4 * 4 + 3][c2] = v.w;
        }
        __syncthreads();
        #pragma unroll
        for (int j4 = 0; j4 < 8; ++j4) {
            float w0v = w1s[j4 * 4 + 0][c];
            float w1v = w1s[j4 * 4 + 1][c];
            float w2v = w1s[j4 * 4 + 2][c];
            float w3v = w1s[j4 * 4 + 3][c];
            #pragma unroll
            for (int r = 0; r < 4; ++r) {
                float4 xv = *(const float4*)&sx[rg * 4 + r][ch * 32 + j4 * 4];
                acc[r] = fmaf(xv.x, w0v, acc[r]);
                acc[r] = fmaf(xv.y, w1v, acc[r]);
                acc[r] = fmaf(xv.z, w2v, acc[r]);
                acc[r] = fmaf(xv.w, w3v, acc[r]);
            }
        }
    }
    float bias = b1[c];
    #pragma unroll
    for (int r = 0; r < 4; ++r) lg[rg * 4 + r][c] = acc[r] + bias;
    __syncthreads();

    // softmax: warp w -> row w
    {
        const int b = bBase + warp;
        float v[4];
        #pragma unroll
        for (int k = 0; k < 4; ++k) v[k] = lg[warp][lane + k * 32];
        // max + argmax (ties -> lowest c)
        float m = v[0]; int am = lane;
        #pragma unroll
        for (int k = 1; k < 4; ++k)
            if (v[k] > m) { m = v[k]; am = lane + k * 32; }
        #pragma unroll
        for (int off = 16; off > 0; off >>= 1) {
            float om = __shfl_xor_sync(0xffffffffu, m, off);
            int oa = __shfl_xor_sync(0xffffffffu, am, off);
            if (om > m || (om == m && oa < am)) { m = om; am = oa; }
        }
        float ssum = 0.f;
        #pragma unroll
        for (int k = 0; k < 4; ++k) ssum += expf(v[k] - m);
        #pragma unroll
        for (int off = 16; off > 0; off >>= 1)
            ssum += __shfl_xor_sync(0xffffffffu, ssum, off);
        const float lse = logf(ssum);
        #pragma unroll
        for (int k = 0; k < 4; ++k)
            out[2 + (size_t)b * NC + lane + k * 32] = v[k] - m - lse;
        const int yb = y[b];
        if (lane == (yb & 31)) g_lossRow[b] = -(v[yb >> 5] - m - lse);
        if (lane == 0) g_corrRow[b] = (am == yb) ? 1.f : 0.f;
    }
}

__global__ void finalize_kernel(float* out) {
    __shared__ float sl[NB], sc[NB];
    int t = threadIdx.x;
    sl[t] = g_lossRow[t];
    sc[t] = g_corrRow[t];
    __syncthreads();
    for (int off = NB / 2; off > 0; off >>= 1) {
        if (t < off) { sl[t] += sl[t + off]; sc[t] += sc[t + off]; }
        __syncthreads();
    }
    if (t == 0) { out[0] = sl[0] / (float)NB; out[1] = sc[0] / (float)NB; }
}

// ---------------- launcher ----------------
extern "C" void kernel_launch(void* const* d_in, const int* in_sizes, int n_in,
                              void* d_out, int out_size) {
    const float* x  = (const float*)d_in[0];
    const int*   y  = (const int*)d_in[1];
    const float* W0 = (const float*)d_in[2];
    const float* b0 = (const float*)d_in[3];
    const float* W1 = (const float*)d_in[4];
    const float* b1 = (const float*)d_in[5];
    float* out = (float*)d_out;

    static cudaStream_t s1;
    static cudaEvent_t eF, eX, eG, eO;
    static bool inited = false;
    if (!inited) {
        cudaStreamCreateWithFlags(&s1, cudaStreamNonBlocking);
        cudaEventCreateWithFlags(&eF, cudaEventDisableTiming);
        cudaEventCreateWithFlags(&eX, cudaEventDisableTiming);
        cudaEventCreateWithFlags(&eG, cudaEventDisableTiming);
        cudaEventCreateWithFlags(&eO, cudaEventDisableTiming);
        cudaFuncSetAttribute(gemm_mma_kernel,
                             cudaFuncAttributeMaxDynamicSharedMemorySize, 4 * STAGE_B);
        inited = true;
    }

    // fork side stream into the capture FIRST, then launch on it
    cudaEventRecord(eF, 0);
    cudaStreamWaitEvent(s1, eF, 0);
    convx_kernel<<<128, 256, 0, s1>>>(x);
    cudaEventRecord(eX, s1);

    convw_kernel<<<4096, 256>>>(W0);
    cudaStreamWaitEvent(0, eX, 0);

    gemm_mma_kernel<<<dim3(64, 4), 256, 4 * STAGE_B>>>(b0);
    cudaEventRecord(eG, 0);

    // side stream: output head (depends only on g_hTop)
    cudaStreamWaitEvent(s1, eG, 0);
    out_kernel<<<NB / 8, 256, 0, s1>>>(W1, b1, y, out);
    finalize_kernel<<<1, NB, 0, s1>>>(out);
    cudaEventRecord(eO, s1);

    // main stream: histogram correction + topKweights
    fixup_kernel<<<64, 256>>>(x, W0, b0);
    topkw_kernel<<<NH, ND>>>(W0, out);
    cudaStreamWaitEvent(0, eO, 0);
}

// round 7
// speedup vs baseline: 2.8399x; 1.0282x over previous
#include <cuda_runtime.h>
#include <cuda_bf16.h>
#include <cstdint>

#define NB 512
#define NS 32
#define NH 512
#define ND 256
#define NC 128
#define KST 512           // compact storage: [hi(256)|lo(256)] per row
#define CAND_CAP 16384
#define CAND_THR 3e-5f

// ---------------- device scratch (static, no allocation) ----------------
__device__ __nv_bfloat16 g_Aext[NB * KST];                  // [b][512] = [xh|xl]
__device__ __nv_bfloat16 g_Bext[(size_t)NS * NH * KST];     // [s*512+h][512] = [wh|wl]
__device__ float g_hTop[NB * NH];                           // relu(max_s z) [b][h]
__device__ int   g_cnt[NH * NS];                            // argmax histogram
__device__ float g_muPart[16][ND];                          // meanUpd partials
__device__ float g_logPart[4][NB * NC];                     // partial logits by h-quarter
__device__ float g_lossRow[NB];
__device__ float g_corrRow[NB];
__device__ int   g_candCount;
__device__ int4  g_cand[CAND_CAP];                          // (b, h, s1, 0)

// ---------------- PTX helpers (plain sm_100 safe) ----------------
__device__ __forceinline__ uint32_t smem_u32(const void* p) {
    uint32_t a;
    asm("{ .reg .u64 t; cvta.to.shared.u64 t, %1; cvt.u32.u64 %0, t; }" : "=r"(a) : "l"(p));
    return a;
}
#define CP_ASYNC16(dst, src) \
    asm volatile("cp.async.cg.shared.global [%0], [%1], 16;" :: "r"(dst), "l"(src) : "memory")
#define CP_COMMIT() asm volatile("cp.async.commit_group;" ::: "memory")
#define CP_WAIT_GROUP(n) asm volatile("cp.async.wait_group %0;" :: "n"(n) : "memory")

__device__ __forceinline__ void ldsm4(uint32_t* r, uint32_t addr) {
    asm volatile("ldmatrix.sync.aligned.m8n8.x4.shared.b16 {%0,%1,%2,%3}, [%4];"
        : "=r"(r[0]), "=r"(r[1]), "=r"(r[2]), "=r"(r[3]) : "r"(addr));
}
__device__ __forceinline__ void mma16816(float* c, const uint32_t* a, const uint32_t* b) {
    asm volatile("mma.sync.aligned.m16n8k16.row.col.f32.bf16.bf16.f32 "
        "{%0,%1,%2,%3}, {%4,%5,%6,%7}, {%8,%9}, {%0,%1,%2,%3};"
        : "+f"(c[0]), "+f"(c[1]), "+f"(c[2]), "+f"(c[3])
        : "r"(a[0]), "r"(a[1]), "r"(a[2]), "r"(a[3]), "r"(b[0]), "r"(b[1]));
}

// swizzled 16B-slot offset inside a [rows][64B] tile (4 slots/row)
__device__ __forceinline__ uint32_t phys64(int row, int c) {
    return (uint32_t)(row * 64 + (((c ^ (row >> 1)) & 3) << 4));
}

// bf16x3 folded-K chunk source offsets (elements), K chunk = 32.
// chunks 0-7: xh*wh, 8-15: xh*wl, 16-23: xl*wh
__device__ __forceinline__ int offA_chunk(int c) {
    return (c < 16) ? (c & 7) * 32 : 256 + (c - 16) * 32;
}
__device__ __forceinline__ int offB_chunk(int c) {
    return ((c >= 8 && c < 16) ? 256 : 0) + (c & 7) * 32;
}

// ---------------- bf16 split helpers ----------------
__device__ __forceinline__ void split2(float a, float b, uint32_t& hi, uint32_t& lo) {
    __nv_bfloat16 h0 = __float2bfloat16_rn(a);
    __nv_bfloat16 h1 = __float2bfloat16_rn(b);
    __nv_bfloat16 l0 = __float2bfloat16_rn(a - __bfloat162float(h0));
    __nv_bfloat16 l1 = __float2bfloat16_rn(b - __bfloat162float(h1));
    __nv_bfloat162 hh; hh.x = h0; hh.y = h1;
    __nv_bfloat162 ll; ll.x = l0; ll.y = l1;
    hi = *(uint32_t*)&hh; lo = *(uint32_t*)&ll;
}

// ---------------- convert x -> A2 (+ meanUpd partials) ----------------
__global__ void convx_kernel(const float* __restrict__ x) {
    int idx = blockIdx.x * 256 + threadIdx.x;   // 0..32767 float4s
    float4 v = ((const float4*)x)[idx];
    int b = idx >> 6, q = idx & 63, d = q * 4;
    uint32_t hA, lA, hB, lB;
    split2(v.x, v.y, hA, lA);
    split2(v.z, v.w, hB, lB);
    uint32_t* base = (uint32_t*)(g_Aext + b * KST);
    uint2 hi2; hi2.x = hA; hi2.y = hB;
    uint2 lo2; lo2.x = lA; lo2.y = lB;
    *(uint2*)(base + (d >> 1)) = hi2;
    *(uint2*)(base + ((256 + d) >> 1)) = lo2;
    if (blockIdx.x < 16) {
        int k = blockIdx.x, dd = threadIdx.x;
        float acc = 0.f;
        #pragma unroll 8
        for (int bb = 0; bb < 32; ++bb) {
            float xv = x[(k * 32 + bb) * ND + dd];
            acc += (xv > 0.f ? 1.f : 0.f) - (xv < 0.f ? 1.f : 0.f);
        }
        g_muPart[k][dd] = acc;
    }
}

// ---------------- W0 -> B2 (+ zero scratch piggyback) ----------------
__global__ void convw_kernel(const float* __restrict__ W0) {
    int bid = blockIdx.x, tid = threadIdx.x;
    if (bid < 16) {
        #pragma unroll
        for (int j = 0; j < 4; ++j) g_cnt[bid * 1024 + j * 256 + tid] = 0;
    } else if (bid == 16 && tid == 0) {
        g_candCount = 0;
    }
    int idx = bid * 256 + tid;                  // 0..1048575 float4s
    float4 v = ((const float4*)W0)[idx];
    int row = idx >> 6, q = idx & 63, d = q * 4;   // row = s*512+h
    uint32_t hA, lA, hB, lB;
    split2(v.x, v.y, hA, lA);
    split2(v.z, v.w, hB, lB);
    uint32_t* base = (uint32_t*)(g_Bext + (size_t)row * KST);
    uint2 hi2; hi2.x = hA; hi2.y = hB;
    uint2 lo2; lo2.x = lA; lo2.y = lB;
    *(uint2*)(base + (d >> 1)) = hi2;
    *(uint2*)(base + ((256 + d) >> 1)) = lo2;
}

// ---------------- mma.sync GEMM + fused max/argmax epilogue ----------------
#define NCHUNK 24
#define STAGE_B 24576

__global__ __launch_bounds__(256, 1)
void gemm_mma_kernel(const float* __restrict__ b0) {
    extern __shared__ char sm[];
    const uint32_t sbase = smem_u32(sm);
    const int tid = threadIdx.x;
    const int lane = tid & 31, warp = tid >> 5;
    const int wb = warp >> 2, wn = warp & 3;
    const int hBase = blockIdx.x * 8;
    const int bTile = blockIdx.y * 128;

    const int prow = tid >> 2, pc = tid & 3;
    const uint32_t dA0 = phys64(prow, pc), dA1 = phys64(prow + 64, pc);
    uint32_t dB[4];
    const __nv_bfloat16* srcB[4];
    #pragma unroll
    for (int r = 0; r < 4; ++r) {
        int n = prow + 64 * r;
        dB[r] = 8192 + phys64(n, pc);
        srcB[r] = g_Bext + (size_t)((n >> 3) * NH + hBase + (n & 7)) * KST + pc * 8;
    }
    const __nv_bfloat16* srcA0 = g_Aext + (size_t)(bTile + prow) * KST + pc * 8;
    const __nv_bfloat16* srcA1 = g_Aext + (size_t)(bTile + prow + 64) * KST + pc * 8;

    uint32_t aOff[2][4], bOff[2][4];
    {
        const int arow = lane & 15, asl = lane >> 4;
        #pragma unroll
        for (int mb = 0; mb < 4; ++mb) {
            int row = wb * 64 + mb * 16 + arow;
            aOff[0][mb] = phys64(row, asl);
            aOff[1][mb] = phys64(row, 2 + asl);
        }
        const int brow = ((lane >> 4) << 3) + (lane & 7), bsl = (lane >> 3) & 1;
        #pragma unroll
        for (int jb = 0; jb < 4; ++jb) {
            int n = wn * 64 + jb * 16 + brow;
            bOff[0][jb] = 8192 + phys64(n, bsl);
            bOff[1][jb] = 8192 + phys64(n, 2 + bsl);
        }
    }

    float acc[4][8][4];
    #pragma unroll
    for (int mb = 0; mb < 4; ++mb)
        #pragma unroll
        for (int nb = 0; nb < 8; ++nb)
            #pragma unroll
            for (int q = 0; q < 4; ++q) acc[mb][nb][q] = 0.f;

    #pragma unroll
    for (int p = 0; p < 3; ++p) {
        uint32_t st = sbase + p * STAGE_B;
        const int oa = offA_chunk(p), ob = offB_chunk(p);
        CP_ASYNC16(st + dA0, srcA0 + oa);
        CP_ASYNC16(st + dA1, srcA1 + oa);
        #pragma unroll
        for (int r = 0; r < 4; ++r) CP_ASYNC16(st + dB[r], srcB[r] + ob);
        CP_COMMIT();
    }

    for (int c = 0; c < NCHUNK; ++c) {
        CP_WAIT_GROUP(2);
        __syncthreads();
        if (c + 3 < NCHUNK) {
            uint32_t st = sbase + ((c + 3) & 3) * STAGE_B;
            const int oa = offA_chunk(c + 3), ob = offB_chunk(c + 3);
            CP_ASYNC16(st + dA0, srcA0 + oa);
            CP_ASYNC16(st + dA1, srcA1 + oa);
            #pragma unroll
            for (int r = 0; r < 4; ++r) CP_ASYNC16(st + dB[r], srcB[r] + ob);
        }
        CP_COMMIT();

        const uint32_t base = sbase + (c & 3) * STAGE_B;
        uint32_t af[2][4][4], bf[2][4][4];
        #pragma unroll
        for (int kh = 0; kh < 2; ++kh) {
            #pragma unroll
            for (int mb = 0; mb < 4; ++mb) ldsm4(af[kh][mb], base + aOff[kh][mb]);
            #pragma unroll
            for (int jb = 0; jb < 4; ++jb) ldsm4(bf[kh][jb], base + bOff[kh][jb]);
        }
        #pragma unroll
        for (int kh = 0; kh < 2; ++kh)
            #pragma unroll
            for (int mb = 0; mb < 4; ++mb)
                #pragma unroll
                for (int jb = 0; jb < 4; ++jb) {
                    mma16816(acc[mb][jb * 2],     af[kh][mb], &bf[kh][jb][0]);
                    mma16816(acc[mb][jb * 2 + 1], af[kh][mb], &bf[kh][jb][2]);
                }
    }
    __syncthreads();

    // ---- epilogue phase 1: per-warp top-2 over this warp's 8 s ----
    float* v1s = (float*)sm;
    int*   s1s = (int*)(sm + 16384);
    float* v2s = (float*)(sm + 32768);

    float biasv[8][2];
    #pragma unroll
    for (int nb = 0; nb < 8; ++nb)
        #pragma unroll
        for (int q = 0; q < 2; ++q)
            biasv[nb][q] = __ldg(&b0[(wn * 8 + nb) * NH + hBase + (lane & 3) * 2 + q]);

    #pragma unroll
    for (int mb = 0; mb < 4; ++mb)
        #pragma unroll
        for (int half = 0; half < 2; ++half)
            #pragma unroll
            for (int q = 0; q < 2; ++q) {
                float m1 = -3.4e38f, m2 = -3.4e38f; int s1 = 0;
                #pragma unroll
                for (int nb = 0; nb < 8; ++nb) {
                    float v = acc[mb][nb][half * 2 + q] + biasv[nb][q];
                    if (v > m1) { m2 = m1; m1 = v; s1 = wn * 8 + nb; }
                    else if (v > m2) m2 = v;
                }
                int row = wb * 64 + mb * 16 + half * 8 + (lane >> 2);
                int hl = (lane & 3) * 2 + q;
                int e = row * 8 + hl;
                v1s[wn * 1024 + e] = m1;
                s1s[wn * 1024 + e] = s1;
                v2s[wn * 1024 + e] = m2;
            }
    __syncthreads();

    // ---- epilogue phase 2: combine, write hTop, hist, candidates ----
    {
        const int e0 = tid * 4;
        float a1v[4][4], a2v[4][4]; int a1s[4][4];
        #pragma unroll
        for (int w = 0; w < 4; ++w) {
            *(float4*)a1v[w] = *(float4*)&v1s[w * 1024 + e0];
            *(int4*)a1s[w]   = *(int4*)&s1s[w * 1024 + e0];
            *(float4*)a2v[w] = *(float4*)&v2s[w * 1024 + e0];
        }
        float relu4[4];
        const int b = bTile + (e0 >> 3);
        #pragma unroll
        for (int k = 0; k < 4; ++k) {
            float m1 = -3.4e38f, m2 = -3.4e38f; int s1 = 0;
            #pragma unroll
            for (int w = 0; w < 4; ++w) {
                float a1 = a1v[w][k], a2 = a2v[w][k];
                if (a1 > m1) { m2 = fmaxf(m1, fmaxf(m2, a2)); m1 = a1; s1 = a1s[w][k]; }
                else { m2 = fmaxf(m2, a1); }
            }
            relu4[k] = fmaxf(m1, 0.f);
            const int h = hBase + ((e0 + k) & 7);
            atomicAdd(&g_cnt[h * NS + s1], 1);
            if (m1 - m2 < CAND_THR) {
                int idx = atomicAdd(&g_candCount, 1);
                if (idx < CAND_CAP) { int4 cd; cd.x = b; cd.y = h; cd.z = s1; cd.w = 0; g_cand[idx] = cd; }
            }
        }
        *(float4*)&g_hTop[(size_t)b * NH + hBase + (e0 & 7)] = *(float4*)relu4;
    }
}

// ---------------- exact fp32 fixup of near-tie argmax decisions ----------------
__global__ void fixup_kernel(const float* __restrict__ x, const float* __restrict__ W0,
                             const float* __restrict__ b0) {
    __shared__ float part[256];
    __shared__ float zrow[NS];
    int cnt = g_candCount; if (cnt > CAND_CAP) cnt = CAND_CAP;
    const int t = threadIdx.x, s = t >> 3, p = t & 7;
    for (int i = blockIdx.x; i < cnt; i += gridDim.x) {
        int4 cd = g_cand[i];
        const float* xr = x + cd.x * ND;
        const float* wr = W0 + (size_t)s * (NH * ND) + cd.y * ND;
        float acc = 0.f;
        #pragma unroll 8
        for (int d = p * 32; d < p * 32 + 32; ++d) acc = fmaf(xr[d], wr[d], acc);
        part[t] = acc;
        __syncthreads();
        if (p == 0) {
            float z = part[t];
            #pragma unroll
            for (int j = 1; j < 8; ++j) z += part[t + j];
            zrow[s] = z + b0[s * NH + cd.y];
        }
        __syncthreads();
        if (t == 0) {
            float m = zrow[0]; int sm_ = 0;
            #pragma unroll
            for (int ss = 1; ss < NS; ++ss)
                if (zrow[ss] > m) { m = zrow[ss]; sm_ = ss; }
            if (sm_ != cd.z) {
                atomicSub(&g_cnt[cd.y * NS + cd.z], 1);
                atomicAdd(&g_cnt[cd.y * NS + sm_], 1);
            }
        }
        __syncthreads();
    }
}

// ---------------- topKweights via histogram-weighted W0 ----------------
__global__ void topkw_kernel(const float* __restrict__ W0, float* __restrict__ out) {
    const int h = blockIdx.x;
    const int d = threadIdx.x;
    __shared__ float cs[NS];
    if (d < NS) cs[d] = (float)g_cnt[h * NS + d];
    __syncthreads();
    float mu = 0.f;
    #pragma unroll
    for (int k = 0; k < 16; ++k) mu += g_muPart[k][d];
    float acc = 0.f;
    #pragma unroll
    for (int s = 0; s < NS; ++s)
        acc = fmaf(cs[s], W0[(size_t)s * (NH * ND) + h * ND + d], acc);
    out[2 + NB * NC + h * ND + d] = acc * (1.f / (float)NB) + mu * (0.001f / (float)NB);
}

// ---------------- output head part 1: partial logits over a 128-h quarter ----
// grid (64 b-groups, 4 h-quarters) x 256 threads. 8 b-rows per block.
__global__ __launch_bounds__(256)
void outpart_kernel(const float* __restrict__ W1) {
    __shared__ float sx[8][NH / 4];    // 4 KB   (this quarter's h slice)
    __shared__ float w1s[32][129];     // 16.5 KB
    const int tid = threadIdx.x;
    const int lane = tid & 31, warp = tid >> 5;
    const int bBase = blockIdx.x * 8;
    const int hq = blockIdx.y;         // h-quarter
    const int hOff = hq * (NH / 4);

    // load 8 x-row slices (8 x 128 floats)
    {
        int i = tid;                   // float4 idx 0..255
        int r = i >> 5, col4 = i & 31;
        ((float4*)sx)[i] = ((const float4*)(g_hTop + (size_t)(bBase + r) * NH + hOff))[col4];
    }

    const int rg = warp >> 2;          // 0/1 -> rows rg*4..rg*4+3
    const int cq = warp & 3;
    const int c = cq * 32 + lane;
    float acc[4] = {0.f, 0.f, 0.f, 0.f};

    for (int ch = 0; ch < 4; ++ch) {
        __syncthreads();
        // load W1 chunk [128 c][32 h] transposed into w1s[h][c]
        #pragma unroll
        for (int k = 0; k < 4; ++k) {
            int i = tid + k * 256;              // float4 idx 0..1023
            int c2 = i >> 3, col4 = i & 7;
            float4 v = ((const float4*)W1)[c2 * (NH / 4) + (hOff >> 2) + ch * 8 + col4];
            w1s[col4 * 4 + 0][c2] = v.x;
            w1s[col4 * 4 + 1][c2] = v.y;
            w1s[col4 * 4 + 2][c2] = v.z;
            w1s[col4 * 4 + 3][c2] = v.w;
        }
        __syncthreads();
        #pragma unroll
        for (int j4 = 0; j4 < 8; ++j4) {
            float w0v = w1s[j4 * 4 + 0][c];
            float w1v = w1s[j4 * 4 + 1][c];
            float w2v = w1s[j4 * 4 + 2][c];
            float w3v = w1s[j4 * 4 + 3][c];
            #pragma unroll
            for (int r = 0; r < 4; ++r) {
                float4 xv = *(const float4*)&sx[rg * 4 + r][ch * 32 + j4 * 4];
                acc[r] = fmaf(xv.x, w0v, acc[r]);
                acc[r] = fmaf(xv.y, w1v, acc[r]);
                acc[r] = fmaf(xv.z, w2v, acc[r]);
                acc[r] = fmaf(xv.w, w3v, acc[r]);
            }
        }
    }
    #pragma unroll
    for (int r = 0; r < 4; ++r)
        g_logPart[hq][(size_t)(bBase + rg * 4 + r) * NC + c] = acc[r];
}

// ---------------- output head part 2: combine + log_softmax ----------------
// grid 64 x 256. warp w -> row bBase+w.
__global__ __launch_bounds__(256)
void softmax_kernel(const float* __restrict__ b1, const int* __restrict__ y,
                    float* __restrict__ out) {
    const int lane = threadIdx.x & 31, warp = threadIdx.x >> 5;
    const int b = blockIdx.x * 8 + warp;
    float v[4];
    #pragma unroll
    for (int k = 0; k < 4; ++k) {
        const int c = lane + k * 32;
        float s = b1[c];
        #pragma unroll
        for (int p = 0; p < 4; ++p) s += g_logPart[p][(size_t)b * NC + c];
        v[k] = s;
    }
    // max + argmax (ties -> lowest c)
    float m = v[0]; int am = lane;
    #pragma unroll
    for (int k = 1; k < 4; ++k)
        if (v[k] > m) { m = v[k]; am = lane + k * 32; }
    #pragma unroll
    for (int off = 16; off > 0; off >>= 1) {
        float om = __shfl_xor_sync(0xffffffffu, m, off);
        int oa = __shfl_xor_sync(0xffffffffu, am, off);
        if (om > m || (om == m && oa < am)) { m = om; am = oa; }
    }
    float ssum = 0.f;
    #pragma unroll
    for (int k = 0; k < 4; ++k) ssum += expf(v[k] - m);
    #pragma unroll
    for (int off = 16; off > 0; off >>= 1)
        ssum += __shfl_xor_sync(0xffffffffu, ssum, off);
    const float lse = logf(ssum);
    #pragma unroll
    for (int k = 0; k < 4; ++k)
        out[2 + (size_t)b * NC + lane + k * 32] = v[k] - m - lse;
    const int yb = y[b];
    if (lane == (yb & 31)) g_lossRow[b] = -(v[yb >> 5] - m - lse);
    if (lane == 0) g_corrRow[b] = (am == yb) ? 1.f : 0.f;
}

__global__ void finalize_kernel(float* out) {
    __shared__ float sl[NB], sc[NB];
    int t = threadIdx.x;
    sl[t] = g_lossRow[t];
    sc[t] = g_corrRow[t];
    __syncthreads();
    for (int off = NB / 2; off > 0; off >>= 1) {
        if (t < off) { sl[t] += sl[t + off]; sc[t] += sc[t + off]; }
        __syncthreads();
    }
    if (t == 0) { out[0] = sl[0] / (float)NB; out[1] = sc[0] / (float)NB; }
}

// ---------------- launcher ----------------
extern "C" void kernel_launch(void* const* d_in, const int* in_sizes, int n_in,
                              void* d_out, int out_size) {
    const float* x  = (const float*)d_in[0];
    const int*   y  = (const int*)d_in[1];
    const float* W0 = (const float*)d_in[2];
    const float* b0 = (const float*)d_in[3];
    const float* W1 = (const float*)d_in[4];
    const float* b1 = (const float*)d_in[5];
    float* out = (float*)d_out;

    static cudaStream_t s1;
    static cudaEvent_t eF, eX, eG, eO;
    static bool inited = false;
    if (!inited) {
        cudaStreamCreateWithFlags(&s1, cudaStreamNonBlocking);
        cudaEventCreateWithFlags(&eF, cudaEventDisableTiming);
        cudaEventCreateWithFlags(&eX, cudaEventDisableTiming);
        cudaEventCreateWithFlags(&eG, cudaEventDisableTiming);
        cudaEventCreateWithFlags(&eO, cudaEventDisableTiming);
        cudaFuncSetAttribute(gemm_mma_kernel,
                             cudaFuncAttributeMaxDynamicSharedMemorySize, 4 * STAGE_B);
        inited = true;
    }

    // fork side stream into the capture first, then launch on it
    cudaEventRecord(eF, 0);
    cudaStreamWaitEvent(s1, eF, 0);
    convx_kernel<<<128, 256, 0, s1>>>(x);
    cudaEventRecord(eX, s1);

    convw_kernel<<<4096, 256>>>(W0);
    cudaStreamWaitEvent(0, eX, 0);

    gemm_mma_kernel<<<dim3(64, 4), 256, 4 * STAGE_B>>>(b0);
    cudaEventRecord(eG, 0);

    // side stream: output head (depends only on g_hTop)
    cudaStreamWaitEvent(s1, eG, 0);
    outpart_kernel<<<dim3(64, 4), 256, 0, s1>>>(W1);
    softmax_kernel<<<64, 256, 0, s1>>>(b1, y, out);
    finalize_kernel<<<1, NB, 0, s1>>>(out);
    cudaEventRecord(eO, s1);

    // main stream: histogram correction + topKweights
    fixup_kernel<<<64, 256>>>(x, W0, b0);
    topkw_kernel<<<NH, ND>>>(W0, out);
    cudaStreamWaitEvent(0, eO, 0);
}